// round 5
// baseline (speedup 1.0000x reference)
#include <cuda_runtime.h>

// GraphConvolution_LEGNN: out = 0.9 * rownorm1(A ⊙ same_class_mask) @ x + 0.1 * h0
// y one-hot -> mask[i][j] = (label[i]==label[j]); A ∈ {0,1}.
// R2: per-class column lists -> gather only ~N/C=625 A entries per row (2.5x less
//     DRAM traffic than streaming the full 40KB row).
// R3: (a) single fused preprocessing kernel (one CTA per class) producing SORTED
//     class lists via ballot-compaction -> ascending-address A gather (DRAM page
//     locality) and 2 launches instead of 3; (b) streaming cache hints on h0/out.
// R4: resubmit (R3 bench died to container infra, kernel never measured).
//
// Inputs: d_in[0]=x [N,F] f32, d_in[1]=A [N,N] f32, d_in[2]=h0 [N,F] f32,
//         d_in[3]=y [N,C] f32.  Output: f32 [N,F].

#define N_NODES 10000
#define F_DIM   256
#define C_CLS   16
#define CAP     1024   // per-row neighbor capacity (expected ~6, worst ~40)
#define PRE_THREADS 256
#define PRE_WARPS   (PRE_THREADS / 32)

__device__ int g_labels[N_NODES];
__device__ int g_ccnt[C_CLS];
__device__ int g_cols[C_CLS * N_NODES];   // per-class sorted column lists

// One CTA per class. Each CTA scans all nodes in order, computes the label from
// the one-hot row (exact dot with iota), and compacts matching node ids into a
// sorted list. CTA 0 additionally writes g_labels.
__global__ __launch_bounds__(PRE_THREADS)
void build_kernel(const float* __restrict__ y) {
    const int c   = blockIdx.x;
    const int tid = threadIdx.x;
    const int wid = tid >> 5;
    const int lid = tid & 31;

    __shared__ int warp_cnt[PRE_WARPS];

    int* __restrict__ dst = g_cols + c * N_NODES;
    int base = 0;  // running output offset, tracked redundantly per thread

    for (int start = 0; start < N_NODES; start += PRE_THREADS) {
        int i = start + tid;
        int lab = -1;
        if (i < N_NODES) {
            const float* yr = y + (size_t)i * C_CLS;
            float s = 0.0f;
#pragma unroll
            for (int k = 0; k < C_CLS; ++k) s = fmaf((float)k, yr[k], s);
            lab = __float2int_rn(s);
            if (c == 0) g_labels[i] = lab;
        }
        bool pred = (lab == c);
        unsigned m = __ballot_sync(0xffffffffu, pred);
        if (lid == 0) warp_cnt[wid] = __popc(m);
        __syncthreads();

        int woff = 0;
#pragma unroll
        for (int w = 0; w < PRE_WARPS; ++w) woff += (w < wid) ? warp_cnt[w] : 0;
        if (pred) dst[base + woff + __popc(m & ((1u << lid) - 1u))] = i;

        int tot = 0;
#pragma unroll
        for (int w = 0; w < PRE_WARPS; ++w) tot += warp_cnt[w];
        base += tot;
        __syncthreads();  // protect warp_cnt reuse next iteration
    }
    if (tid == 0) g_ccnt[c] = base;
}

__global__ __launch_bounds__(F_DIM)
void gcn_row_kernel(const float* __restrict__ x,
                    const float* __restrict__ A,
                    const float* __restrict__ h0,
                    float* __restrict__ out) {
    __shared__ int   s_idx[CAP];
    __shared__ float s_val[CAP];
    __shared__ int   s_cnt;

    const int row = blockIdx.x;
    const int tid = threadIdx.x;

    if (tid == 0) s_cnt = 0;
    __syncthreads();

    const int myc  = g_labels[row];
    const int ccnt = g_ccnt[myc];
    const int* __restrict__ clist = g_cols + myc * N_NODES;
    const float* __restrict__ Arow = A + (size_t)row * N_NODES;

    // Gather only same-class columns of this A row. clist is sorted, so the
    // warp walks the row in ascending address order (~64B stride) -> good DRAM
    // page locality. A is read once: streaming hint.
    for (int k = tid; k < ccnt; k += F_DIM) {
        int col  = __ldg(&clist[k]);
        float av = __ldcs(&Arow[col]);
        if (av != 0.0f) {
            int p = atomicAdd(&s_cnt, 1);
            if (p < CAP) {
                s_idx[p] = col;
                s_val[p] = av;
            }
        }
    }
    __syncthreads();

    const int cnt = min(s_cnt, CAP);

    // Drain: thread tid owns feature column tid (F == blockDim). x stays
    // L2-resident (10MB) and is shared across all rows of the class.
    float acc = 0.0f, sumw = 0.0f;
    int k = 0;
    for (; k + 4 <= cnt; k += 4) {
        int   c0 = s_idx[k],     c1 = s_idx[k + 1];
        int   c2 = s_idx[k + 2], c3 = s_idx[k + 3];
        float w0 = s_val[k],     w1 = s_val[k + 1];
        float w2 = s_val[k + 2], w3 = s_val[k + 3];
        float v0 = __ldg(&x[(size_t)c0 * F_DIM + tid]);
        float v1 = __ldg(&x[(size_t)c1 * F_DIM + tid]);
        float v2 = __ldg(&x[(size_t)c2 * F_DIM + tid]);
        float v3 = __ldg(&x[(size_t)c3 * F_DIM + tid]);
        acc  += w0 * v0 + w1 * v1 + w2 * v2 + w3 * v3;
        sumw += w0 + w1 + w2 + w3;
    }
    for (; k < cnt; ++k) {
        float w = s_val[k];
        acc  += w * __ldg(&x[(size_t)s_idx[k] * F_DIM + tid]);
        sumw += w;
    }

    float rs = fmaxf(sumw, 1e-12f);
    size_t o = (size_t)row * F_DIM + tid;
    // h0/out are pure streams: keep them out of L2's way.
    out[o] = 0.9f * (acc / rs) + 0.1f * __ldcs(&h0[o]);
}

extern "C" void kernel_launch(void* const* d_in, const int* in_sizes, int n_in,
                              void* d_out, int out_size) {
    const float* x  = (const float*)d_in[0];
    const float* A  = (const float*)d_in[1];
    const float* h0 = (const float*)d_in[2];
    const float* y  = (const float*)d_in[3];
    float* out = (float*)d_out;

    build_kernel<<<C_CLS, PRE_THREADS>>>(y);
    gcn_row_kernel<<<N_NODES, F_DIM>>>(x, A, h0, out);
}

// round 7
// speedup vs baseline: 1.6340x; 1.6340x over previous
#include <cuda_runtime.h>

// GraphConvolution_LEGNN: out = 0.9 * rownorm1(A ⊙ same_class_mask) @ x + 0.1 * h0
// y one-hot -> mask[i][j] = (label[i]==label[j]); A ∈ {0,1}.
// R2: per-class column lists -> gather only ~N/C=625 A entries per row.
// R5: cheap parallel prep + class-grouped CTA->row mapping (concurrent CTAs
//     share the same ~625 x-rows -> x stays hot in L2).
// R6: FIX the class-prefix mapping (R5's scan could spuriously re-advance on
//     later small classes -> rows misassigned, rel_err 0.21). Latch first class
//     with b < cumulative count.
//
// Inputs: d_in[0]=x [N,F] f32, d_in[1]=A [N,N] f32, d_in[2]=h0 [N,F] f32,
//         d_in[3]=y [N,C] f32.  Output: f32 [N,F].

#define N_NODES 10000
#define F_DIM   256
#define C_CLS   16
#define CAP     1024   // per-row neighbor capacity (expected ~6, worst ~40)

__device__ int g_ccnt[C_CLS];
__device__ int g_cols[C_CLS * N_NODES];   // per-class column lists (unordered)

__global__ void zero_kernel() {
    if (threadIdx.x < C_CLS) g_ccnt[threadIdx.x] = 0;
}

// Wide parallel build: label from one-hot row (exact iota dot), atomic scatter
// into this class's list. Order within a class is irrelevant.
__global__ __launch_bounds__(256)
void prep_kernel(const float* __restrict__ y) {
    int i = blockIdx.x * blockDim.x + threadIdx.x;
    if (i >= N_NODES) return;
    const float* yr = y + (size_t)i * C_CLS;
    float s = 0.0f;
#pragma unroll
    for (int k = 0; k < C_CLS; ++k) s = fmaf((float)k, yr[k], s);
    int lab = __float2int_rn(s);
    int p = atomicAdd(&g_ccnt[lab], 1);
    g_cols[lab * N_NODES + p] = i;
}

__global__ __launch_bounds__(F_DIM)
void gcn_row_kernel(const float* __restrict__ x,
                    const float* __restrict__ A,
                    const float* __restrict__ h0,
                    float* __restrict__ out) {
    __shared__ int   s_idx[CAP];
    __shared__ float s_val[CAP];
    __shared__ int   s_cnt;

    const int b   = blockIdx.x;
    const int tid = threadIdx.x;

    if (tid == 0) s_cnt = 0;

    // Class-grouped scheduling: block b handles the b-th node in class order.
    // Correct scan: latch the FIRST class where b < cumulative count.
    int cum = 0, off = 0, myc = C_CLS - 1;
    bool found = false;
#pragma unroll
    for (int cc = 0; cc < C_CLS; ++cc) {
        int prev = cum;
        cum += g_ccnt[cc];
        if (!found && b < cum) { myc = cc; off = prev; found = true; }
    }
    const int ccnt = g_ccnt[myc];
    const int* __restrict__ clist = g_cols + myc * N_NODES;
    const int row = clist[b - off];

    __syncthreads();  // s_cnt init visible

    const float* __restrict__ Arow = A + (size_t)row * N_NODES;

    // Gather only same-class columns of this A row (~625 scattered LDG.32).
    // A is read once: evict-first so it can't push the hot x set out of L2.
    for (int k = tid; k < ccnt; k += F_DIM) {
        int col  = __ldg(&clist[k]);
        float av = __ldcs(&Arow[col]);
        if (av != 0.0f) {
            int p = atomicAdd(&s_cnt, 1);
            if (p < CAP) {
                s_idx[p] = col;
                s_val[p] = av;
            }
        }
    }
    __syncthreads();

    const int cnt = min(s_cnt, CAP);

    // Drain: thread tid owns feature column tid. Concurrent CTAs are all in the
    // same class -> these x rows (~625KB) stay hot in L2.
    float acc = 0.0f, sumw = 0.0f;
    int k = 0;
    for (; k + 4 <= cnt; k += 4) {
        int   c0 = s_idx[k],     c1 = s_idx[k + 1];
        int   c2 = s_idx[k + 2], c3 = s_idx[k + 3];
        float w0 = s_val[k],     w1 = s_val[k + 1];
        float w2 = s_val[k + 2], w3 = s_val[k + 3];
        float v0 = __ldg(&x[(size_t)c0 * F_DIM + tid]);
        float v1 = __ldg(&x[(size_t)c1 * F_DIM + tid]);
        float v2 = __ldg(&x[(size_t)c2 * F_DIM + tid]);
        float v3 = __ldg(&x[(size_t)c3 * F_DIM + tid]);
        acc  += w0 * v0 + w1 * v1 + w2 * v2 + w3 * v3;
        sumw += w0 + w1 + w2 + w3;
    }
    for (; k < cnt; ++k) {
        float w = s_val[k];
        acc  += w * __ldg(&x[(size_t)s_idx[k] * F_DIM + tid]);
        sumw += w;
    }

    float rs = fmaxf(sumw, 1e-12f);
    size_t o = (size_t)row * F_DIM + tid;
    out[o] = 0.9f * (acc / rs) + 0.1f * __ldcs(&h0[o]);
}

extern "C" void kernel_launch(void* const* d_in, const int* in_sizes, int n_in,
                              void* d_out, int out_size) {
    const float* x  = (const float*)d_in[0];
    const float* A  = (const float*)d_in[1];
    const float* h0 = (const float*)d_in[2];
    const float* y  = (const float*)d_in[3];
    float* out = (float*)d_out;

    zero_kernel<<<1, 32>>>();
    prep_kernel<<<(N_NODES + 255) / 256, 256>>>(y);
    gcn_row_kernel<<<N_NODES, F_DIM>>>(x, A, h0, out);
}

// round 8
// speedup vs baseline: 1.7302x; 1.0589x over previous
#include <cuda_runtime.h>

// GraphConvolution_LEGNN: out = 0.9 * rownorm1(A ⊙ same_class_mask) @ x + 0.1 * h0
// y one-hot -> mask[i][j] = (label[i]==label[j]); A ∈ {0,1}.
// R2: per-class column lists -> gather only ~N/C=625 A entries per row.
// R6 lessons: x is always L2-resident (10MB vs 126MB) -> class-grouped
//   scheduling is worthless; row-order scheduling was fastest. Launch overhead
//   matters (~3.4us for a 16-int zero kernel).
// R7: (a) 2 launches: last main block resets counters via atomic ticket;
//     (b) high-MLP gather: preload <=3 list entries then issue all A-loads
//         back-to-back (ccnt < 768 always for this distribution; tail loop kept
//         for generality).
//
// Inputs: d_in[0]=x [N,F] f32, d_in[1]=A [N,N] f32, d_in[2]=h0 [N,F] f32,
//         d_in[3]=y [N,C] f32.  Output: f32 [N,F].

#define N_NODES 10000
#define F_DIM   256
#define C_CLS   16
#define CAP     1024   // per-row neighbor capacity (expected ~6, worst ~40)

__device__ int g_labels[N_NODES];
__device__ int g_ccnt[C_CLS];          // zero at module load; self-reset each launch
__device__ int g_done;                 // ticket; zero at load; self-reset
__device__ int g_cols[C_CLS * N_NODES];

// Wide parallel prep: label from one-hot row (exact iota dot), write labels,
// atomic scatter into class list (order irrelevant).
__global__ __launch_bounds__(256)
void prep_kernel(const float* __restrict__ y) {
    int i = blockIdx.x * blockDim.x + threadIdx.x;
    if (i >= N_NODES) return;
    const float* yr = y + (size_t)i * C_CLS;
    float s = 0.0f;
#pragma unroll
    for (int k = 0; k < C_CLS; ++k) s = fmaf((float)k, yr[k], s);
    int lab = __float2int_rn(s);
    g_labels[i] = lab;
    int p = atomicAdd(&g_ccnt[lab], 1);
    g_cols[lab * N_NODES + p] = i;
}

__global__ __launch_bounds__(F_DIM)
void gcn_row_kernel(const float* __restrict__ x,
                    const float* __restrict__ A,
                    const float* __restrict__ h0,
                    float* __restrict__ out) {
    __shared__ int   s_idx[CAP];
    __shared__ float s_val[CAP];
    __shared__ int   s_cnt;

    const int row = blockIdx.x;
    const int tid = threadIdx.x;

    if (tid == 0) s_cnt = 0;
    __syncthreads();

    const int myc  = g_labels[row];
    const int ccnt = g_ccnt[myc];
    const int* __restrict__ clist = g_cols + myc * N_NODES;
    const float* __restrict__ Arow = A + (size_t)row * N_NODES;

    // High-MLP gather: each thread owns list slots tid, tid+256, tid+512.
    // Load all list entries, then fire all A loads back-to-back so the LSU has
    // 3 independent DRAM requests in flight per thread. A read once: evict-first.
    {
        const int k0 = tid, k1 = tid + F_DIM, k2 = tid + 2 * F_DIM;
        const bool p0 = k0 < ccnt, p1 = k1 < ccnt, p2 = k2 < ccnt;
        int c0 = 0, c1 = 0, c2 = 0;
        if (p0) c0 = __ldg(&clist[k0]);
        if (p1) c1 = __ldg(&clist[k1]);
        if (p2) c2 = __ldg(&clist[k2]);
        float a0 = 0.0f, a1 = 0.0f, a2 = 0.0f;
        if (p0) a0 = __ldcs(&Arow[c0]);
        if (p1) a1 = __ldcs(&Arow[c1]);
        if (p2) a2 = __ldcs(&Arow[c2]);
        if (a0 != 0.0f) { int p = atomicAdd(&s_cnt, 1); if (p < CAP) { s_idx[p] = c0; s_val[p] = a0; } }
        if (a1 != 0.0f) { int p = atomicAdd(&s_cnt, 1); if (p < CAP) { s_idx[p] = c1; s_val[p] = a1; } }
        if (a2 != 0.0f) { int p = atomicAdd(&s_cnt, 1); if (p < CAP) { s_idx[p] = c2; s_val[p] = a2; } }
        // Generality tail (not taken for this distribution: ccnt ~ 625 +/- 24).
        for (int k = 3 * F_DIM + tid; k < ccnt; k += F_DIM) {
            int col  = __ldg(&clist[k]);
            float av = __ldcs(&Arow[col]);
            if (av != 0.0f) { int p = atomicAdd(&s_cnt, 1); if (p < CAP) { s_idx[p] = col; s_val[p] = av; } }
        }
    }
    __syncthreads();

    const int cnt = min(s_cnt, CAP);

    // Drain: thread tid owns feature column tid; x rows are L2 hits.
    float acc = 0.0f, sumw = 0.0f;
    int k = 0;
    for (; k + 4 <= cnt; k += 4) {
        int   c0 = s_idx[k],     c1 = s_idx[k + 1];
        int   c2 = s_idx[k + 2], c3 = s_idx[k + 3];
        float w0 = s_val[k],     w1 = s_val[k + 1];
        float w2 = s_val[k + 2], w3 = s_val[k + 3];
        float v0 = __ldg(&x[(size_t)c0 * F_DIM + tid]);
        float v1 = __ldg(&x[(size_t)c1 * F_DIM + tid]);
        float v2 = __ldg(&x[(size_t)c2 * F_DIM + tid]);
        float v3 = __ldg(&x[(size_t)c3 * F_DIM + tid]);
        acc  += w0 * v0 + w1 * v1 + w2 * v2 + w3 * v3;
        sumw += w0 + w1 + w2 + w3;
    }
    for (; k < cnt; ++k) {
        float w = s_val[k];
        acc  += w * __ldg(&x[(size_t)s_idx[k] * F_DIM + tid]);
        sumw += w;
    }

    float rs = fmaxf(sumw, 1e-12f);
    size_t o = (size_t)row * F_DIM + tid;
    out[o] = 0.9f * (acc / rs) + 0.1f * __ldcs(&h0[o]);

    // Self-reset for next graph replay: last block to finish zeroes the
    // counters. All of this block's g_ccnt reads precede the ticket (sync +
    // program order), so no block can observe the reset early.
    __syncthreads();
    if (tid == 0) {
        __threadfence();
        int t = atomicAdd(&g_done, 1);
        if (t == gridDim.x - 1) {
#pragma unroll
            for (int c = 0; c < C_CLS; ++c) g_ccnt[c] = 0;
            g_done = 0;
        }
    }
}

extern "C" void kernel_launch(void* const* d_in, const int* in_sizes, int n_in,
                              void* d_out, int out_size) {
    const float* x  = (const float*)d_in[0];
    const float* A  = (const float*)d_in[1];
    const float* h0 = (const float*)d_in[2];
    const float* y  = (const float*)d_in[3];
    float* out = (float*)d_out;

    prep_kernel<<<(N_NODES + 255) / 256, 256>>>(y);
    gcn_row_kernel<<<N_NODES, F_DIM>>>(x, A, h0, out);
}